// round 6
// baseline (speedup 1.0000x reference)
#include <cuda_runtime.h>
#include <cstdint>

#define BC      128            // B*C = 8*16
#define B_DIM   8
#define C_DIM   16
#define HW      147456         // 384*384
#define HW4     36864          // HW/4 (float4 per class)
#define SPLIT   24
#define CHUNK4  (HW4 / SPLIT)  // 1536 float4 = 24KB per array per block
#define NTHREADS 256
#define NBLOCKS (BC * SPLIT)   // 3072

#define SUB4    (CHUNK4 / 2)   // 768 float4 = 12KB sub-tile per array
#define SUB_B   (SUB4 * 16)    // 12288 bytes

#define ALPHA   0.05f
#define SMOOTH  1e-6f

// scratch: [NBLOCKS][5] partials: {sum_d2t, sum_d2, sum_t, max_t, max_p}
__device__ float g_part[NBLOCKS * 5];
__device__ int   g_count = 0;

__device__ __forceinline__ uint32_t smem_u32(const void* p) {
    return (uint32_t)__cvta_generic_to_shared(p);
}
__device__ __forceinline__ void mbar_init(uint32_t mbar, uint32_t count) {
    asm volatile("mbarrier.init.shared.b64 [%0], %1;" :: "r"(mbar), "r"(count) : "memory");
}
__device__ __forceinline__ void mbar_expect_tx(uint32_t mbar, uint32_t bytes) {
    asm volatile("mbarrier.arrive.expect_tx.shared.b64 _, [%0], %1;"
                 :: "r"(mbar), "r"(bytes) : "memory");
}
__device__ __forceinline__ void mbar_wait(uint32_t mbar, uint32_t parity) {
    asm volatile(
        "{\n\t.reg .pred P;\n\t"
        "W%=: mbarrier.try_wait.parity.acquire.cta.shared::cta.b64 P, [%0], %1;\n\t"
        "@!P bra W%=;\n\t}"
        :: "r"(mbar), "r"(parity) : "memory");
}
__device__ __forceinline__ void bulk_cp(uint32_t dst_smem, const void* src, uint32_t bytes,
                                        uint32_t mbar) {
    asm volatile(
        "cp.async.bulk.shared::cta.global.mbarrier::complete_tx::bytes [%0], [%1], %2, [%3];"
        :: "r"(dst_smem), "l"(src), "r"(bytes), "r"(mbar) : "memory");
}

__global__ __launch_bounds__(NTHREADS)
void fused_kernel(const float4* __restrict__ no,
                  const float4* __restrict__ tg,
                  const float4* __restrict__ mp,
                  float* __restrict__ out)
{
    // 48KB tiles + barriers -> 4 CTAs/SM, up to 192KB TMA in flight per SM
    __shared__ __align__(128) float4 sm_t[CHUNK4];
    __shared__ __align__(128) float4 sm_n[CHUNK4];
    __shared__ __align__(8)   uint64_t sm_bar[2];

    const int cls  = blockIdx.x / SPLIT;
    const int part = blockIdx.x % SPLIT;
    const long base = (long)cls * HW4 + (long)part * CHUNK4;

    const int wid = threadIdx.x >> 5;
    const int lid = threadIdx.x & 31;
    const int NW  = NTHREADS / 32;

    // issue the ENTIRE chunk immediately: 2 sub-tiles x (t + n)
    if (threadIdx.x == 0) {
        mbar_init(smem_u32(&sm_bar[0]), 1);
        mbar_init(smem_u32(&sm_bar[1]), 1);
        asm volatile("fence.proxy.async.shared::cta;" ::: "memory");
        #pragma unroll
        for (int s = 0; s < 2; s++) {
            uint32_t bar = smem_u32(&sm_bar[s]);
            mbar_expect_tx(bar, 2 * SUB_B);
            bulk_cp(smem_u32(&sm_t[s * SUB4]), tg + base + s * SUB4, SUB_B, bar);
            bulk_cp(smem_u32(&sm_n[s * SUB4]), no + base + s * SUB4, SUB_B, bar);
        }
    }
    __syncthreads();

    float s_d2t = 0.f, s_d2 = 0.f, s_t = 0.f;
    float mxt = -1e30f;

    #pragma unroll
    for (int s = 0; s < 2; s++) {
        mbar_wait(smem_u32(&sm_bar[s]), 0u);
        #pragma unroll
        for (int r = 0; r < SUB4 / NTHREADS; r++) {
            float4 t = sm_t[s * SUB4 + r * NTHREADS + threadIdx.x];
            float4 n = sm_n[s * SUB4 + r * NTHREADS + threadIdx.x];
            float d;
            d = t.x - n.x; float d2x = d * d;
            d = t.y - n.y; float d2y = d * d;
            d = t.z - n.z; float d2z = d * d;
            d = t.w - n.w; float d2w = d * d;
            s_d2  += d2x + d2y + d2z + d2w;
            s_d2t += d2x * t.x + d2y * t.y + d2z * t.z + d2w * t.w;
            s_t   += t.x + t.y + t.z + t.w;
            mxt = fmaxf(mxt, fmaxf(fmaxf(t.x, t.y), fmaxf(t.z, t.w)));
        }
    }

    #pragma unroll
    for (int off = 16; off > 0; off >>= 1) {
        s_d2t += __shfl_xor_sync(0xffffffff, s_d2t, off);
        s_d2  += __shfl_xor_sync(0xffffffff, s_d2,  off);
        s_t   += __shfl_xor_sync(0xffffffff, s_t,   off);
        mxt = fmaxf(mxt, __shfl_xor_sync(0xffffffff, mxt, off));
    }

    __shared__ float sh[NTHREADS / 32][4];
    __shared__ float sh_blkmax;
    if (lid == 0) {
        sh[wid][0] = s_d2t; sh[wid][1] = s_d2; sh[wid][2] = s_t; sh[wid][3] = mxt;
    }
    __syncthreads();

    if (wid == 0) {
        float v0 = (lid < NW) ? sh[lid][0] : 0.f;
        float v1 = (lid < NW) ? sh[lid][1] : 0.f;
        float v2 = (lid < NW) ? sh[lid][2] : 0.f;
        float v3 = (lid < NW) ? sh[lid][3] : -1e30f;
        #pragma unroll
        for (int off = 4; off > 0; off >>= 1) {
            v0 += __shfl_xor_sync(0xffffffff, v0, off);
            v1 += __shfl_xor_sync(0xffffffff, v1, off);
            v2 += __shfl_xor_sync(0xffffffff, v2, off);
            v3 = fmaxf(v3, __shfl_xor_sync(0xffffffff, v3, off));
        }
        if (lid == 0) {
            sh[0][0] = v0; sh[0][1] = v1; sh[0][2] = v2;
            sh_blkmax = v3;
        }
    }
    __syncthreads();

    // rare pass: mp only matters if this block's target chunk is all-zero
    // (if any t>0, the class is active and this block's mxp is never consulted)
    float mxp = -1e30f;
    if (sh_blkmax == 0.0f) {
        const float4* pp = mp + base + threadIdx.x;
        #pragma unroll
        for (int k = 0; k < CHUNK4 / NTHREADS; k++) {
            float4 p = __ldcs(pp + k * NTHREADS);
            mxp = fmaxf(mxp, fmaxf(fmaxf(p.x, p.y), fmaxf(p.z, p.w)));
        }
        #pragma unroll
        for (int off = 16; off > 0; off >>= 1)
            mxp = fmaxf(mxp, __shfl_xor_sync(0xffffffff, mxp, off));
        __shared__ float shp[NTHREADS / 32];
        if (lid == 0) shp[wid] = mxp;
        __syncthreads();
        if (wid == 0) {
            float v = (lid < NW) ? shp[lid] : -1e30f;
            #pragma unroll
            for (int off = 4; off > 0; off >>= 1)
                v = fmaxf(v, __shfl_xor_sync(0xffffffff, v, off));
            mxp = v;
        }
    }

    __shared__ bool s_last;
    if (threadIdx.x == 0) {
        float* dst = &g_part[(long)blockIdx.x * 5];
        dst[0] = sh[0][0]; dst[1] = sh[0][1]; dst[2] = sh[0][2];
        dst[3] = sh_blkmax; dst[4] = mxp;
        __threadfence();
        int old = atomicAdd(&g_count, 1);
        s_last = (old == NBLOCKS - 1);
    }
    __syncthreads();

    if (!s_last) return;

    // ---- fused epilogue: last block reduces all partials ----
    __shared__ float losses[BC];
    __shared__ float imgl[B_DIM];

    if (threadIdx.x < BC) {
        const int c = threadIdx.x;
        float a_d2t = 0.f, a_d2 = 0.f, a_t = 0.f;
        float a_mt = -1e30f, a_mp = -1e30f;
        #pragma unroll
        for (int j = 0; j < SPLIT; j++) {
            const float* src = &g_part[(long)(c * SPLIT + j) * 5];
            a_d2t += __ldcg(src + 0);
            a_d2  += __ldcg(src + 1);
            a_t   += __ldcg(src + 2);
            a_mt = fmaxf(a_mt, __ldcg(src + 3));
            a_mp = fmaxf(a_mp, __ldcg(src + 4));
        }
        float m1 = a_d2t;
        float m2 = a_d2 - a_d2t;
        float d1 = a_t;
        float d2 = (float)HW - a_t;
        float loss = ALPHA * m1 / (d1 + SMOOTH) + (1.0f - ALPHA) * m2 / (d2 + SMOOTH);
        bool active = !((a_mt == 0.0f) && (a_mp == 0.0f));
        losses[c] = active ? loss : 0.0f;
    }
    __syncthreads();

    if (threadIdx.x < B_DIM) {
        float s = 0.f, cnt = 0.f;
        #pragma unroll
        for (int c = 0; c < C_DIM; c++) {
            float v = losses[threadIdx.x * C_DIM + c];
            s += v;
            if (v != 0.0f) cnt += 1.0f;
        }
        imgl[threadIdx.x] = s / cnt;
    }
    __syncthreads();

    if (threadIdx.x == 0) {
        float s = 0.f;
        #pragma unroll
        for (int b = 0; b < B_DIM; b++) s += imgl[b];
        out[0] = s / (float)B_DIM;
        g_count = 0;   // reset for next graph replay (deterministic)
    }
}

extern "C" void kernel_launch(void* const* d_in, const int* in_sizes, int n_in,
                              void* d_out, int out_size)
{
    const float4* no = (const float4*)d_in[0];   // net_out
    const float4* tg = (const float4*)d_in[1];   // target
    const float4* mp = (const float4*)d_in[2];   // max_positiones

    fused_kernel<<<NBLOCKS, NTHREADS>>>(no, tg, mp, (float*)d_out);
}

// round 7
// speedup vs baseline: 1.4672x; 1.4672x over previous
#include <cuda_runtime.h>

#define BC      128            // B*C = 8*16
#define B_DIM   8
#define C_DIM   16
#define HW      147456         // 384*384
#define HW4     36864          // HW/4 (float4 per class)
#define SPLIT   6              // blocks per class
#define BLK4    (HW4 / SPLIT)  // 6144 float4 per block per array
#define HALF4   (BLK4 / 2)     // 3072
#define NTHREADS 256
#define ITERS   (HALF4 / NTHREADS)   // 12
#define NBLOCKS (BC * SPLIT)         // 768

#define ALPHA   0.05f
#define SMOOTH  1e-6f

// scratch: [NBLOCKS][5] partials: {sum_d2t, sum_d2, sum_t, max_t, max_p}
__device__ float g_part[NBLOCKS * 5];
__device__ int   g_count = 0;

__global__ __launch_bounds__(NTHREADS)
void fused_kernel(const float4* __restrict__ no,
                  const float4* __restrict__ tg,
                  const float4* __restrict__ mp,
                  float* __restrict__ out)
{
    const int cls  = blockIdx.x / SPLIT;
    const int part = blockIdx.x % SPLIT;
    const long base = (long)cls * HW4 + (long)part * BLK4;

    const int wid = threadIdx.x >> 5;
    const int lid = threadIdx.x & 31;
    const int NW  = NTHREADS / 32;

    float s_d2t = 0.f, s_d2 = 0.f, s_t = 0.f;
    float mxt = -1e30f;

    const float4* tl = tg + base + threadIdx.x;
    const float4* th = tg + base + HALF4 + threadIdx.x;
    const float4* nl = no + base + threadIdx.x;
    const float4* nh = no + base + HALF4 + threadIdx.x;

    // 4 independent load streams per iteration (R1-style loop, all bytes useful)
    for (int k = 0; k < ITERS; k++) {
        const int idx = k * NTHREADS;
        float4 t0 = tl[idx];
        float4 t1 = th[idx];
        float4 n0 = nl[idx];
        float4 n1 = nh[idx];

        float d;
        d = t0.x - n0.x; float a0 = d * d;
        d = t0.y - n0.y; float a1 = d * d;
        d = t0.z - n0.z; float a2 = d * d;
        d = t0.w - n0.w; float a3 = d * d;
        s_d2  += a0 + a1 + a2 + a3;
        s_d2t += a0 * t0.x + a1 * t0.y + a2 * t0.z + a3 * t0.w;
        s_t   += t0.x + t0.y + t0.z + t0.w;
        mxt = fmaxf(mxt, fmaxf(fmaxf(t0.x, t0.y), fmaxf(t0.z, t0.w)));

        d = t1.x - n1.x; float b0 = d * d;
        d = t1.y - n1.y; float b1 = d * d;
        d = t1.z - n1.z; float b2 = d * d;
        d = t1.w - n1.w; float b3 = d * d;
        s_d2  += b0 + b1 + b2 + b3;
        s_d2t += b0 * t1.x + b1 * t1.y + b2 * t1.z + b3 * t1.w;
        s_t   += t1.x + t1.y + t1.z + t1.w;
        mxt = fmaxf(mxt, fmaxf(fmaxf(t1.x, t1.y), fmaxf(t1.z, t1.w)));
    }

    #pragma unroll
    for (int off = 16; off > 0; off >>= 1) {
        s_d2t += __shfl_xor_sync(0xffffffff, s_d2t, off);
        s_d2  += __shfl_xor_sync(0xffffffff, s_d2,  off);
        s_t   += __shfl_xor_sync(0xffffffff, s_t,   off);
        mxt = fmaxf(mxt, __shfl_xor_sync(0xffffffff, mxt, off));
    }

    __shared__ float sh[NTHREADS / 32][4];
    __shared__ float sh_blkmax;
    if (lid == 0) {
        sh[wid][0] = s_d2t; sh[wid][1] = s_d2; sh[wid][2] = s_t; sh[wid][3] = mxt;
    }
    __syncthreads();

    if (wid == 0) {
        float v0 = (lid < NW) ? sh[lid][0] : 0.f;
        float v1 = (lid < NW) ? sh[lid][1] : 0.f;
        float v2 = (lid < NW) ? sh[lid][2] : 0.f;
        float v3 = (lid < NW) ? sh[lid][3] : -1e30f;
        #pragma unroll
        for (int off = 4; off > 0; off >>= 1) {
            v0 += __shfl_xor_sync(0xffffffff, v0, off);
            v1 += __shfl_xor_sync(0xffffffff, v1, off);
            v2 += __shfl_xor_sync(0xffffffff, v2, off);
            v3 = fmaxf(v3, __shfl_xor_sync(0xffffffff, v3, off));
        }
        if (lid == 0) {
            sh[0][0] = v0; sh[0][1] = v1; sh[0][2] = v2;
            sh_blkmax = v3;
        }
    }
    __syncthreads();

    // rare pass: mp only matters if this block's target region is all-zero
    // (if any t>0, the class is active and this block's mxp is never consulted)
    float mxp = -1e30f;
    if (sh_blkmax == 0.0f) {
        const float4* pp = mp + base + threadIdx.x;
        for (int k = 0; k < BLK4 / NTHREADS; k++) {
            float4 p = pp[k * NTHREADS];
            mxp = fmaxf(mxp, fmaxf(fmaxf(p.x, p.y), fmaxf(p.z, p.w)));
        }
        #pragma unroll
        for (int off = 16; off > 0; off >>= 1)
            mxp = fmaxf(mxp, __shfl_xor_sync(0xffffffff, mxp, off));
        __shared__ float shp[NTHREADS / 32];
        if (lid == 0) shp[wid] = mxp;
        __syncthreads();
        if (wid == 0) {
            float v = (lid < NW) ? shp[lid] : -1e30f;
            #pragma unroll
            for (int off = 4; off > 0; off >>= 1)
                v = fmaxf(v, __shfl_xor_sync(0xffffffff, v, off));
            mxp = v;
        }
    }

    __shared__ bool s_last;
    if (threadIdx.x == 0) {
        float* dst = &g_part[(long)blockIdx.x * 5];
        dst[0] = sh[0][0]; dst[1] = sh[0][1]; dst[2] = sh[0][2];
        dst[3] = sh_blkmax; dst[4] = mxp;
        __threadfence();
        int old = atomicAdd(&g_count, 1);
        s_last = (old == NBLOCKS - 1);
    }
    __syncthreads();

    if (!s_last) return;

    // ---- fused epilogue: last block reduces all partials ----
    __shared__ float losses[BC];
    __shared__ float imgl[B_DIM];

    if (threadIdx.x < BC) {
        const int c = threadIdx.x;
        float a_d2t = 0.f, a_d2 = 0.f, a_t = 0.f;
        float a_mt = -1e30f, a_mp = -1e30f;
        #pragma unroll
        for (int j = 0; j < SPLIT; j++) {
            const float* src = &g_part[(long)(c * SPLIT + j) * 5];
            a_d2t += __ldcg(src + 0);
            a_d2  += __ldcg(src + 1);
            a_t   += __ldcg(src + 2);
            a_mt = fmaxf(a_mt, __ldcg(src + 3));
            a_mp = fmaxf(a_mp, __ldcg(src + 4));
        }
        float m1 = a_d2t;
        float m2 = a_d2 - a_d2t;
        float d1 = a_t;
        float d2 = (float)HW - a_t;
        float loss = ALPHA * m1 / (d1 + SMOOTH) + (1.0f - ALPHA) * m2 / (d2 + SMOOTH);
        bool active = !((a_mt == 0.0f) && (a_mp == 0.0f));
        losses[c] = active ? loss : 0.0f;
    }
    __syncthreads();

    if (threadIdx.x < B_DIM) {
        float s = 0.f, cnt = 0.f;
        #pragma unroll
        for (int c = 0; c < C_DIM; c++) {
            float v = losses[threadIdx.x * C_DIM + c];
            s += v;
            if (v != 0.0f) cnt += 1.0f;
        }
        imgl[threadIdx.x] = s / cnt;
    }
    __syncthreads();

    if (threadIdx.x == 0) {
        float s = 0.f;
        #pragma unroll
        for (int b = 0; b < B_DIM; b++) s += imgl[b];
        out[0] = s / (float)B_DIM;
        g_count = 0;   // reset for next graph replay (deterministic)
    }
}

extern "C" void kernel_launch(void* const* d_in, const int* in_sizes, int n_in,
                              void* d_out, int out_size)
{
    const float4* no = (const float4*)d_in[0];   // net_out
    const float4* tg = (const float4*)d_in[1];   // target
    const float4* mp = (const float4*)d_in[2];   // max_positiones

    fused_kernel<<<NBLOCKS, NTHREADS>>>(no, tg, mp, (float*)d_out);
}